// round 2
// baseline (speedup 1.0000x reference)
#include <cuda_runtime.h>
#include <cstdint>
#include <cstddef>

#define BATCH 64
#define SEQ   2048
#define IND   128
#define HID   256
#define OUTD  64
#define M_ROWS (SEQ*BATCH)

// ---------------- scratch (static device globals; no cudaMalloc allowed) ----------------
__device__ float g_bufA[(size_t)SEQ * BATCH * HID];   // 128 MiB
__device__ float g_bufH[(size_t)SEQ * BATCH * HID];   // 128 MiB
__device__ float g_T1[HID * HID];
__device__ float g_Wc[OUTD * HID];
__device__ float g_b12[HID];
__device__ float g_bc[OUTD];

// ---------------- tiny head-folding kernels ----------------
// T1 = fc2W @ fc1W ; b12 = fc2W @ fc1b + fc2b
__global__ void combine1_kernel(const float* __restrict__ fc2W, const float* __restrict__ fc1W,
                                const float* __restrict__ fc1b, const float* __restrict__ fc2b) {
    int i = blockIdx.x, k = threadIdx.x;
    float acc = 0.f;
    for (int j = 0; j < HID; ++j) acc += fc2W[i * HID + j] * fc1W[j * HID + k];
    g_T1[i * HID + k] = acc;
    if (k == 0) {
        float s = 0.f;
        for (int j = 0; j < HID; ++j) s += fc2W[i * HID + j] * fc1b[j];
        g_b12[i] = s + fc2b[i];
    }
}

// Wc = fc3W @ T1 ; bc = fc3W @ b12 + fc3b
__global__ void combine2_kernel(const float* __restrict__ fc3W, const float* __restrict__ fc3b) {
    int o = blockIdx.x, k = threadIdx.x;
    float acc = 0.f;
    for (int j = 0; j < HID; ++j) acc += fc3W[o * HID + j] * g_T1[j * HID + k];
    g_Wc[o * HID + k] = acc;
    if (k == 0) {
        float s = 0.f;
        for (int j = 0; j < HID; ++j) s += fc3W[o * HID + j] * g_b12[j];
        g_bc[o] = s + fc3b[o];
    }
}

// ---------------- generic fp32 SIMT GEMM: C[m][n] = sum_k A[m][k]*Bw[n][k] + bias ----------------
// amode 0: A row m at Ap + m*K
// amode 1: (x gather) m = t*BATCH + b -> row at Ap + (b*SEQ + t)*K
// omode 0: C row m at Cp + m*N
// omode 1: (final transpose) m = t*BATCH + b -> Cp + (b*SEQ + t)*N
__global__ void __launch_bounds__(256)
gemm_kernel(const float* __restrict__ Ap, const float* __restrict__ Bw,
            const float* __restrict__ bias1, const float* __restrict__ bias2,
            float* __restrict__ Cp, int N, int K, int amode, int omode) {
    __shared__ __align__(16) float As[16][128];
    __shared__ __align__(16) float Bs[16][64];
    const int tid = threadIdx.x;
    const int bm = blockIdx.x * 128;
    const int bn = blockIdx.y * 64;
    const int tx = tid & 15, ty = tid >> 4;

    // A tile loader setup: 128 rows x 16 k = 512 float4 slots, 2 per thread
    const float* arow[2];
    int amm[2], akq[2];
#pragma unroll
    for (int it = 0; it < 2; ++it) {
        int slot = tid + it * 256;
        amm[it] = slot >> 2;
        akq[it] = slot & 3;
        int m = bm + amm[it];
        if (amode) {
            int bb = m & 63;
            int tt = m >> 6;
            arow[it] = Ap + ((size_t)bb * SEQ + tt) * K;
        } else {
            arow[it] = Ap + (size_t)m * K;
        }
    }
    const int bnn = tid >> 2, bkq = tid & 3;
    const float* brow = Bw + (size_t)(bn + bnn) * K;

    float acc[8][4];
#pragma unroll
    for (int i = 0; i < 8; ++i)
#pragma unroll
        for (int j = 0; j < 4; ++j) acc[i][j] = 0.f;

    for (int k0 = 0; k0 < K; k0 += 16) {
#pragma unroll
        for (int it = 0; it < 2; ++it) {
            float4 v = *(const float4*)(arow[it] + k0 + akq[it] * 4);
            As[akq[it] * 4 + 0][amm[it]] = v.x;
            As[akq[it] * 4 + 1][amm[it]] = v.y;
            As[akq[it] * 4 + 2][amm[it]] = v.z;
            As[akq[it] * 4 + 3][amm[it]] = v.w;
        }
        {
            float4 v = *(const float4*)(brow + k0 + bkq * 4);
            Bs[bkq * 4 + 0][bnn] = v.x;
            Bs[bkq * 4 + 1][bnn] = v.y;
            Bs[bkq * 4 + 2][bnn] = v.z;
            Bs[bkq * 4 + 3][bnn] = v.w;
        }
        __syncthreads();
#pragma unroll
        for (int kk = 0; kk < 16; ++kk) {
            float4 b4 = *(const float4*)&Bs[kk][tx * 4];
            float4 x0 = *(const float4*)&As[kk][ty * 8];
            float4 x1 = *(const float4*)&As[kk][ty * 8 + 4];
            float av[8] = {x0.x, x0.y, x0.z, x0.w, x1.x, x1.y, x1.z, x1.w};
            float bv[4] = {b4.x, b4.y, b4.z, b4.w};
#pragma unroll
            for (int i = 0; i < 8; ++i)
#pragma unroll
                for (int j = 0; j < 4; ++j) acc[i][j] = fmaf(av[i], bv[j], acc[i][j]);
        }
        __syncthreads();
    }

    float bb[4];
#pragma unroll
    for (int j = 0; j < 4; ++j) {
        int n = bn + tx * 4 + j;
        float v = bias1 ? bias1[n] : 0.f;
        if (bias2) v += bias2[n];
        bb[j] = v;
    }
#pragma unroll
    for (int i = 0; i < 8; ++i) {
        int m = bm + ty * 8 + i;
        float4 v;
        v.x = acc[i][0] + bb[0];
        v.y = acc[i][1] + bb[1];
        v.z = acc[i][2] + bb[2];
        v.w = acc[i][3] + bb[3];
        float* dst;
        if (omode == 1) {
            int bb2 = m & 63;
            int tt = m >> 6;
            dst = Cp + ((size_t)bb2 * SEQ + tt) * N + bn + tx * 4;
        } else {
            dst = Cp + (size_t)m * N + bn + tx * 4;
        }
        *(float4*)dst = v;
    }
}

// ---------------- persistent RNN scan: h[t] = tanh(A[t] + W @ h[t-1]) per batch ----------------
// One 2-CTA cluster per batch element. Each CTA owns output rows [rank*128, rank*128+128),
// weights register-resident (64/thread), h exchanged via DSMEM + 1 cluster barrier/step.
__device__ __forceinline__ void cluster_sync_() {
    asm volatile("barrier.cluster.arrive.aligned;" ::: "memory");
    asm volatile("barrier.cluster.wait.aligned;" ::: "memory");
}

__global__ void __cluster_dims__(2, 1, 1) __launch_bounds__(512, 1)
scan_kernel(const float* __restrict__ A, const float* __restrict__ W, float* __restrict__ Hout) {
    __shared__ __align__(16) float h_sm[2][HID];
    __shared__ float part_sm[4][128];
    const int tid = threadIdx.x;
    uint32_t rank;
    asm("mov.u32 %0, %%cluster_ctarank;" : "=r"(rank));
    const int b = blockIdx.x >> 1;
    const int jl = tid & 127;
    const int kq = tid >> 7;
    const int jg = (int)rank * 128 + jl;

    // register-resident weight slice: W[jg][kq*64 .. kq*64+64)
    float wreg[64];
    {
        const float* wsrc = W + (size_t)jg * HID + kq * 64;
#pragma unroll
        for (int i = 0; i < 64; i += 4) {
            float4 v = *(const float4*)(wsrc + i);
            wreg[i] = v.x; wreg[i + 1] = v.y; wreg[i + 2] = v.z; wreg[i + 3] = v.w;
        }
    }

    if (tid < HID) h_sm[0][tid] = 0.f;
    __syncthreads();
    cluster_sync_();

    // peer CTA's h_sm base (DSMEM)
    uint32_t hs_local = (uint32_t)__cvta_generic_to_shared(&h_sm[0][0]);
    uint32_t hs_peer;
    asm("mapa.shared::cluster.u32 %0, %1, %2;" : "=r"(hs_peer) : "r"(hs_local), "r"(rank ^ 1u));

    const float* Abase = A + (size_t)b * HID + jg;
    float* Hbase = Hout + (size_t)b * HID + jg;
    int p = 0;
    for (int t = 0; t < SEQ; ++t) {
        float aval = 0.f;
        if (tid < 128) aval = __ldg(Abase + (size_t)t * (BATCH * HID));  // prefetch, hidden under dot

        const float* hc = &h_sm[p][kq * 64];
        float a0 = 0.f, a1 = 0.f, a2 = 0.f, a3 = 0.f;
#pragma unroll
        for (int i = 0; i < 64; i += 4) {
            float4 hv = *(const float4*)(hc + i);  // broadcast LDS.128
            a0 = fmaf(wreg[i],     hv.x, a0);
            a1 = fmaf(wreg[i + 1], hv.y, a1);
            a2 = fmaf(wreg[i + 2], hv.z, a2);
            a3 = fmaf(wreg[i + 3], hv.w, a3);
        }
        part_sm[kq][jl] = (a0 + a1) + (a2 + a3);
        __syncthreads();
        if (tid < 128) {
            float s = part_sm[0][jl] + part_sm[1][jl] + part_sm[2][jl] + part_sm[3][jl] + aval;
            float hv = tanhf(s);
            int np = p ^ 1;
            h_sm[np][jg] = hv;
            uint32_t raddr = hs_peer + (uint32_t)((np * HID + jg) * 4);
            asm volatile("st.shared::cluster.f32 [%0], %1;" :: "r"(raddr), "f"(hv) : "memory");
            Hbase[(size_t)t * (BATCH * HID)] = hv;  // fire-and-forget
        }
        cluster_sync_();  // release/acquire at cluster scope: orders DSMEM stores vs next reads
        p ^= 1;
    }
}

// ---------------- launcher ----------------
extern "C" void kernel_launch(void* const* d_in, const int* in_sizes, int n_in,
                              void* d_out, int out_size) {
    const float* x    = (const float*)d_in[0];
    const float* U0   = (const float*)d_in[1];
    const float* bU0  = (const float*)d_in[2];
    const float* W0   = (const float*)d_in[3];
    const float* bW0  = (const float*)d_in[4];
    const float* U1   = (const float*)d_in[5];
    const float* bU1  = (const float*)d_in[6];
    const float* W1   = (const float*)d_in[7];
    const float* bW1  = (const float*)d_in[8];
    const float* fc1W = (const float*)d_in[9];
    const float* fc1b = (const float*)d_in[10];
    const float* fc2W = (const float*)d_in[11];
    const float* fc2b = (const float*)d_in[12];
    const float* fc3W = (const float*)d_in[13];
    const float* fc3b = (const float*)d_in[14];
    float* out = (float*)d_out;

    float *pA, *pH, *pWc, *pbc;
    cudaGetSymbolAddress((void**)&pA, g_bufA);
    cudaGetSymbolAddress((void**)&pH, g_bufH);
    cudaGetSymbolAddress((void**)&pWc, g_Wc);
    cudaGetSymbolAddress((void**)&pbc, g_bc);

    // fold the 3-layer FC head into one 64x256 matrix + bias
    combine1_kernel<<<HID, HID>>>(fc2W, fc1W, fc1b, fc2b);
    combine2_kernel<<<OUTD, HID>>>(fc3W, fc3b);

    // A0[t,b,:] = x[b,t,:] @ U0^T + bU0 + bW0
    gemm_kernel<<<dim3(M_ROWS / 128, HID / 64), 256>>>(x, U0, bU0, bW0, pA, HID, IND, 1, 0);
    // scan layer 0: h0_all -> g_bufH
    scan_kernel<<<BATCH * 2, 512>>>(pA, W0, pH);
    // A1 = h0_all @ U1^T + bU1 + bW1 -> g_bufA
    gemm_kernel<<<dim3(M_ROWS / 128, HID / 64), 256>>>(pH, U1, bU1, bW1, pA, HID, HID, 0, 0);
    // scan layer 1: outs -> g_bufH (h0 no longer needed)
    scan_kernel<<<BATCH * 2, 512>>>(pA, W1, pH);
    // head: out[b,t,:] = outs[t,b,:] @ Wc^T + bc, written transposed
    gemm_kernel<<<dim3(M_ROWS / 128, OUTD / 64), 256>>>(pH, pWc, pbc, nullptr, out, OUTD, HID, 0, 1);
}

// round 3
// speedup vs baseline: 1.0558x; 1.0558x over previous
#include <cuda_runtime.h>
#include <cstdint>
#include <cstddef>

#define BATCH 64
#define SEQ   2048
#define IND   128
#define HID   256
#define OUTD  64
#define M_ROWS (SEQ*BATCH)

typedef unsigned long long ull;

// ---------------- scratch ----------------
__device__ float g_bufA[(size_t)SEQ * BATCH * HID];
__device__ float g_bufH[(size_t)SEQ * BATCH * HID];
__device__ float g_T1[HID * HID];
__device__ float g_Wc[OUTD * HID];
__device__ float g_b12[HID];
__device__ float g_bc[OUTD];

// ---------------- f32x2 helpers ----------------
__device__ __forceinline__ void ffma2(ull& acc, ull a, ull b) {
    asm("fma.rn.f32x2 %0, %1, %2, %0;" : "+l"(acc) : "l"(a), "l"(b));
}
__device__ __forceinline__ ull pack2(float x, float y) {
    ull r; asm("mov.b64 %0, {%1,%2};" : "=l"(r) : "f"(x), "f"(y)); return r;
}
__device__ __forceinline__ float2 unpack2(ull v) {
    float2 r; asm("mov.b64 {%0,%1}, %2;" : "=f"(r.x), "=f"(r.y) : "l"(v)); return r;
}
__device__ __forceinline__ void lds_v2u64(ull& a, ull& b, uint32_t addr) {
    asm volatile("ld.shared.v2.u64 {%0,%1}, [%2];" : "=l"(a), "=l"(b) : "r"(addr));
}

// ---------------- head folding ----------------
__global__ void combine1_kernel(const float* __restrict__ fc2W, const float* __restrict__ fc1W,
                                const float* __restrict__ fc1b, const float* __restrict__ fc2b) {
    int i = blockIdx.x, k = threadIdx.x;
    float acc = 0.f;
    for (int j = 0; j < HID; ++j) acc += fc2W[i * HID + j] * fc1W[j * HID + k];
    g_T1[i * HID + k] = acc;
    if (k == 0) {
        float s = 0.f;
        for (int j = 0; j < HID; ++j) s += fc2W[i * HID + j] * fc1b[j];
        g_b12[i] = s + fc2b[i];
    }
}
__global__ void combine2_kernel(const float* __restrict__ fc3W, const float* __restrict__ fc3b) {
    int o = blockIdx.x, k = threadIdx.x;
    float acc = 0.f;
    for (int j = 0; j < HID; ++j) acc += fc3W[o * HID + j] * g_T1[j * HID + k];
    g_Wc[o * HID + k] = acc;
    if (k == 0) {
        float s = 0.f;
        for (int j = 0; j < HID; ++j) s += fc3W[o * HID + j] * g_b12[j];
        g_bc[o] = s + fc3b[o];
    }
}

// ---------------- f32x2 SIMT GEMM ----------------
// C[m][n] = sum_k A[m][k]*Bw[n][k] + bias. BM=128, BN=TN, BK=16, 256 threads,
// microtile MT x 8 per thread, accumulators packed f32x2.
template<int TN, int MT, int AMODE, int OMODE>
__global__ void __launch_bounds__(256)
gemm_kernel(const float* __restrict__ Ap, const float* __restrict__ Bw,
            const float* __restrict__ bias1, const float* __restrict__ bias2,
            float* __restrict__ Cp, int K) {
    __shared__ __align__(16) float As[16][128];
    __shared__ __align__(16) float Bs[16][TN];
    constexpr int NX = TN / 8;
    const int tid = threadIdx.x;
    const int bm = blockIdx.x * 128;
    const int bn = blockIdx.y * TN;
    const int tx = tid % NX, ty = tid / NX;

    // A tile loader: 128x16 = 512 float4 slots, 2/thread
    const float* arow[2]; int amm[2], akq[2];
#pragma unroll
    for (int it = 0; it < 2; ++it) {
        int slot = tid + it * 256;
        amm[it] = slot >> 2; akq[it] = slot & 3;
        int m = bm + amm[it];
        if (AMODE) arow[it] = Ap + ((size_t)(m & 63) * SEQ + (m >> 6)) * K;
        else       arow[it] = Ap + (size_t)m * K;
    }
    // B tile loader: TN x 16 floats
    constexpr int BLD = TN / 64;
    const float* brow[BLD]; int bnn[BLD], bkq[BLD];
#pragma unroll
    for (int it = 0; it < BLD; ++it) {
        int slot = tid + it * 256;
        bnn[it] = slot >> 2; bkq[it] = slot & 3;
        brow[it] = Bw + (size_t)(bn + bnn[it]) * K;
    }

    ull acc[MT][4];
#pragma unroll
    for (int i = 0; i < MT; ++i)
#pragma unroll
        for (int j = 0; j < 4; ++j) acc[i][j] = 0ull;

    uint32_t bs_base = (uint32_t)__cvta_generic_to_shared(&Bs[0][0]);

    for (int k0 = 0; k0 < K; k0 += 16) {
#pragma unroll
        for (int it = 0; it < 2; ++it) {
            float4 v = *(const float4*)(arow[it] + k0 + akq[it] * 4);
            As[akq[it] * 4 + 0][amm[it]] = v.x;
            As[akq[it] * 4 + 1][amm[it]] = v.y;
            As[akq[it] * 4 + 2][amm[it]] = v.z;
            As[akq[it] * 4 + 3][amm[it]] = v.w;
        }
#pragma unroll
        for (int it = 0; it < BLD; ++it) {
            float4 v = *(const float4*)(brow[it] + k0 + bkq[it] * 4);
            Bs[bkq[it] * 4 + 0][bnn[it]] = v.x;
            Bs[bkq[it] * 4 + 1][bnn[it]] = v.y;
            Bs[bkq[it] * 4 + 2][bnn[it]] = v.z;
            Bs[bkq[it] * 4 + 3][bnn[it]] = v.w;
        }
        __syncthreads();
#pragma unroll
        for (int kk = 0; kk < 16; ++kk) {
            ull b0, b1, b2, b3;
            uint32_t ba = bs_base + (uint32_t)((kk * TN + tx * 8) * 4);
            lds_v2u64(b0, b1, ba);
            lds_v2u64(b2, b3, ba + 16);
            float av[MT];
#pragma unroll
            for (int q = 0; q < MT; q += 4) {
                float4 a4 = *(const float4*)&As[kk][ty * MT + q];
                av[q] = a4.x; av[q + 1] = a4.y; av[q + 2] = a4.z; av[q + 3] = a4.w;
            }
#pragma unroll
            for (int i = 0; i < MT; ++i) {
                ull ad = pack2(av[i], av[i]);
                ffma2(acc[i][0], ad, b0);
                ffma2(acc[i][1], ad, b1);
                ffma2(acc[i][2], ad, b2);
                ffma2(acc[i][3], ad, b3);
            }
        }
        __syncthreads();
    }

    float bb[8];
#pragma unroll
    for (int j = 0; j < 8; ++j) {
        int n = bn + tx * 8 + j;
        float v = bias1 ? bias1[n] : 0.f;
        if (bias2) v += bias2[n];
        bb[j] = v;
    }
#pragma unroll
    for (int i = 0; i < MT; ++i) {
        int m = bm + ty * MT + i;
        float2 p0 = unpack2(acc[i][0]), p1 = unpack2(acc[i][1]);
        float2 p2 = unpack2(acc[i][2]), p3 = unpack2(acc[i][3]);
        float4 v0 = {p0.x + bb[0], p0.y + bb[1], p1.x + bb[2], p1.y + bb[3]};
        float4 v1 = {p2.x + bb[4], p2.y + bb[5], p3.x + bb[6], p3.y + bb[7]};
        float* dst;
        if (OMODE) dst = Cp + ((size_t)(m & 63) * SEQ + (m >> 6)) * TN * blockDim.y // unused path guard
                       ;
        if (OMODE) dst = Cp + ((size_t)(m & 63) * SEQ + (m >> 6)) * OUTD + bn + tx * 8;
        else       dst = Cp + (size_t)m * (gridDim.y * TN) + bn + tx * 8;
        *(float4*)dst = v0;
        *(float4*)(dst + 4) = v1;
    }
}

// ---------------- persistent RNN scan ----------------
__device__ __forceinline__ void cluster_sync_() {
    asm volatile("barrier.cluster.arrive.aligned;" ::: "memory");
    asm volatile("barrier.cluster.wait.aligned;" ::: "memory");
}
__device__ __forceinline__ void mbar_wait_cluster(uint32_t mb, int ph) {
    asm volatile(
        "{\n\t.reg .pred P;\n"
        "W1_%=:\n\t"
        "mbarrier.try_wait.parity.acquire.cluster.shared::cta.b64 P, [%0], %1, 0x989680;\n\t"
        "@P bra W2_%=;\n\t"
        "bra W1_%=;\n"
        "W2_%=:\n\t}"
        :: "r"(mb), "r"(ph) : "memory");
}

__global__ void __cluster_dims__(2, 1, 1) __launch_bounds__(512, 1)
scan_kernel(const float* __restrict__ A, const float* __restrict__ W, float* __restrict__ Hout) {
    __shared__ __align__(16) float h_sm[2][HID];
    __shared__ __align__(16) float part_sm[4][128];
    __shared__ __align__(8) ull mbar[2];
    const int tid = threadIdx.x;
    uint32_t rank;
    asm("mov.u32 %0, %%cluster_ctarank;" : "=r"(rank));
    const int b = blockIdx.x >> 1;
    const int jl = tid & 127;
    const int kq = tid >> 7;
    const int jg = (int)rank * 128 + jl;
    const int kLbase = (int)rank * 128 + kq * 32;        // locally-produced h half
    const int kRbase = (int)(rank ^ 1u) * 128 + kq * 32; // peer-produced h half

    // register-resident weights: 32 floats local-half + 32 remote-half as f32x2
    ull wL[16], wR[16];
    {
        const float* ws = W + (size_t)jg * HID;
#pragma unroll
        for (int i = 0; i < 16; i += 2) {
            float4 v = *(const float4*)(ws + kLbase + i * 2);
            wL[i] = pack2(v.x, v.y); wL[i + 1] = pack2(v.z, v.w);
            float4 u = *(const float4*)(ws + kRbase + i * 2);
            wR[i] = pack2(u.x, u.y); wR[i + 1] = pack2(u.z, u.w);
        }
    }

    uint32_t h_local = (uint32_t)__cvta_generic_to_shared(&h_sm[0][0]);
    uint32_t mb_local = (uint32_t)__cvta_generic_to_shared(&mbar[0]);
    uint32_t h_peer, mb_peer;
    asm("mapa.shared::cluster.u32 %0, %1, %2;" : "=r"(h_peer) : "r"(h_local), "r"(rank ^ 1u));
    asm("mapa.shared::cluster.u32 %0, %1, %2;" : "=r"(mb_peer) : "r"(mb_local), "r"(rank ^ 1u));

    if (tid == 0) {
        asm volatile("mbarrier.init.shared.b64 [%0], %1;" :: "r"(mb_local), "r"(1) : "memory");
        asm volatile("mbarrier.init.shared.b64 [%0], %1;" :: "r"(mb_local + 8), "r"(1) : "memory");
    }
    __syncthreads();
    cluster_sync_();  // peer mbarriers initialized before any remote arrive

    const float* Abase = A + (size_t)b * HID + jg;
    float* Hbase = Hout + (size_t)b * HID + jg;

    float acur = 0.f, anext = 0.f;
    // ---- prologue: t = 0, h_prev = 0 -> h = tanh(A[0]) ----
    if (tid < 128) {
        acur = __ldg(Abase);
        float hv = tanhf(acur);
        h_sm[1][jg] = hv;
        uint32_t ra = h_peer + (uint32_t)((HID + jg) * 4);
        asm volatile("st.shared::cluster.f32 [%0], %1;" :: "r"(ra), "f"(hv) : "memory");
        Hbase[0] = hv;
        anext = __ldg(Abase + (size_t)BATCH * HID);  // t=1 prefetch
    }
    __syncthreads();
    if (tid == 0) {
        asm volatile("mbarrier.arrive.release.cluster.shared::cluster.b64 _, [%0];"
                     :: "r"(mb_peer + 8) : "memory");
    }

    int ph0 = 0, ph1 = 0;
    for (int t = 1; t < SEQ; ++t) {
        const int p = t & 1;
        acur = anext;
        if (tid < 128) {
            int tn = (t + 1 < SEQ) ? (t + 1) : (SEQ - 1);
            anext = __ldg(Abase + (size_t)tn * (BATCH * HID));
        }
        // ---- dot over locally-produced half (no cluster wait needed) ----
        uint32_t hbL = h_local + (uint32_t)((p * HID + kLbase) * 4);
        ull a0 = 0ull, a1 = 0ull, a2 = 0ull, a3 = 0ull;
#pragma unroll
        for (int i = 0; i < 8; ++i) {
            ull x0, x1;
            lds_v2u64(x0, x1, hbL + (uint32_t)(i * 16));
            if (i & 1) { ffma2(a2, wL[2 * i], x0); ffma2(a3, wL[2 * i + 1], x1); }
            else       { ffma2(a0, wL[2 * i], x0); ffma2(a1, wL[2 * i + 1], x1); }
        }
        // ---- wait for peer's half of h[t-1] ----
        if (p) { mbar_wait_cluster(mb_local + 8, ph1); ph1 ^= 1; }
        else   { mbar_wait_cluster(mb_local,     ph0); ph0 ^= 1; }
        // ---- dot over peer-produced half ----
        uint32_t hbR = h_local + (uint32_t)((p * HID + kRbase) * 4);
#pragma unroll
        for (int i = 0; i < 8; ++i) {
            ull x0, x1;
            lds_v2u64(x0, x1, hbR + (uint32_t)(i * 16));
            if (i & 1) { ffma2(a2, wR[2 * i], x0); ffma2(a3, wR[2 * i + 1], x1); }
            else       { ffma2(a0, wR[2 * i], x0); ffma2(a1, wR[2 * i + 1], x1); }
        }
        float2 s0 = unpack2(a0), s1 = unpack2(a1), s2 = unpack2(a2), s3 = unpack2(a3);
        part_sm[kq][jl] = ((s0.x + s0.y) + (s1.x + s1.y)) + ((s2.x + s2.y) + (s3.x + s3.y));
        __syncthreads();
        const int np = p ^ 1;
        if (tid < 128) {
            float s = part_sm[0][jl] + part_sm[1][jl] + part_sm[2][jl] + part_sm[3][jl] + acur;
            float hv = tanhf(s);
            h_sm[np][jg] = hv;
            uint32_t ra = h_peer + (uint32_t)((np * HID + jg) * 4);
            asm volatile("st.shared::cluster.f32 [%0], %1;" :: "r"(ra), "f"(hv) : "memory");
            Hbase[(size_t)t * (BATCH * HID)] = hv;
        }
        __syncthreads();  // orders all writers' stores before the single release-arrive
        if (tid == 0) {
            uint32_t rm = mb_peer + (uint32_t)(np * 8);
            asm volatile("mbarrier.arrive.release.cluster.shared::cluster.b64 _, [%0];"
                         :: "r"(rm) : "memory");
        }
    }
    cluster_sync_();  // keep smem alive for in-flight peer traffic
}

// ---------------- launcher ----------------
extern "C" void kernel_launch(void* const* d_in, const int* in_sizes, int n_in,
                              void* d_out, int out_size) {
    const float* x    = (const float*)d_in[0];
    const float* U0   = (const float*)d_in[1];
    const float* bU0  = (const float*)d_in[2];
    const float* W0   = (const float*)d_in[3];
    const float* bW0  = (const float*)d_in[4];
    const float* U1   = (const float*)d_in[5];
    const float* bU1  = (const float*)d_in[6];
    const float* W1   = (const float*)d_in[7];
    const float* bW1  = (const float*)d_in[8];
    const float* fc1W = (const float*)d_in[9];
    const float* fc1b = (const float*)d_in[10];
    const float* fc2W = (const float*)d_in[11];
    const float* fc2b = (const float*)d_in[12];
    const float* fc3W = (const float*)d_in[13];
    const float* fc3b = (const float*)d_in[14];
    float* out = (float*)d_out;

    float *pA, *pH, *pWc, *pbc;
    cudaGetSymbolAddress((void**)&pA, g_bufA);
    cudaGetSymbolAddress((void**)&pH, g_bufH);
    cudaGetSymbolAddress((void**)&pWc, g_Wc);
    cudaGetSymbolAddress((void**)&pbc, g_bc);

    combine1_kernel<<<HID, HID>>>(fc2W, fc1W, fc1b, fc2b);
    combine2_kernel<<<OUTD, HID>>>(fc3W, fc3b);

    // A0[t,b,:] = x[b,t,:] @ U0^T + bU0 + bW0
    gemm_kernel<128, 8, 1, 0><<<dim3(M_ROWS / 128, HID / 128), 256>>>(x, U0, bU0, bW0, pA, IND);
    scan_kernel<<<BATCH * 2, 512>>>(pA, W0, pH);
    // A1 = h0_all @ U1^T + bU1 + bW1
    gemm_kernel<128, 8, 0, 0><<<dim3(M_ROWS / 128, HID / 128), 256>>>(pH, U1, bU1, bW1, pA, HID);
    scan_kernel<<<BATCH * 2, 512>>>(pA, W1, pH);
    // head: out[b,t,:] = outs[t,b,:] @ Wc^T + bc (N=64)
    gemm_kernel<64, 4, 0, 1><<<dim3(M_ROWS / 128, 1), 256>>>(pH, pWc, pbc, nullptr, out, HID);
}

// round 5
// speedup vs baseline: 1.1360x; 1.0760x over previous
#include <cuda_runtime.h>
#include <cstdint>
#include <cstddef>

#define BATCH 64
#define SEQ   2048
#define IND   128
#define HID   256
#define OUTD  64
#define M_ROWS (SEQ*BATCH)

typedef unsigned long long ull;

// ---------------- scratch ----------------
__device__ float g_bufA[(size_t)SEQ * BATCH * HID];
__device__ float g_bufH[(size_t)SEQ * BATCH * HID];
__device__ float g_T1[HID * HID];
__device__ float g_Wc[OUTD * HID];
__device__ float g_b12[HID];
__device__ float g_bc[OUTD];

// ---------------- f32x2 helpers ----------------
__device__ __forceinline__ void ffma2(ull& acc, ull a, ull b) {
    asm("fma.rn.f32x2 %0, %1, %2, %0;" : "+l"(acc) : "l"(a), "l"(b));
}
__device__ __forceinline__ ull pack2(float x, float y) {
    ull r; asm("mov.b64 %0, {%1,%2};" : "=l"(r) : "f"(x), "f"(y)); return r;
}
__device__ __forceinline__ float2 unpack2(ull v) {
    float2 r; asm("mov.b64 {%0,%1}, %2;" : "=f"(r.x), "=f"(r.y) : "l"(v)); return r;
}
__device__ __forceinline__ void lds_v2u64(ull& a, ull& b, uint32_t addr) {
    asm volatile("ld.shared.v2.u64 {%0,%1}, [%2];" : "=l"(a), "=l"(b) : "r"(addr));
}
// fast tanh: 1 - 2/(exp(2x)+1); MUFU-based, rel err ~1e-6, saturates correctly
__device__ __forceinline__ float tanh_fast(float x) {
    float e = __expf(2.f * x);
    return 1.f - __fdividef(2.f, e + 1.f);
}

// ---------------- head folding ----------------
__global__ void combine1_kernel(const float* __restrict__ fc2W, const float* __restrict__ fc1W,
                                const float* __restrict__ fc1b, const float* __restrict__ fc2b) {
    int i = blockIdx.x, k = threadIdx.x;
    float acc = 0.f;
    for (int j = 0; j < HID; ++j) acc += fc2W[i * HID + j] * fc1W[j * HID + k];
    g_T1[i * HID + k] = acc;
    if (k == 0) {
        float s = 0.f;
        for (int j = 0; j < HID; ++j) s += fc2W[i * HID + j] * fc1b[j];
        g_b12[i] = s + fc2b[i];
    }
}
__global__ void combine2_kernel(const float* __restrict__ fc3W, const float* __restrict__ fc3b) {
    int o = blockIdx.x, k = threadIdx.x;
    float acc = 0.f;
    for (int j = 0; j < HID; ++j) acc += fc3W[o * HID + j] * g_T1[j * HID + k];
    g_Wc[o * HID + k] = acc;
    if (k == 0) {
        float s = 0.f;
        for (int j = 0; j < HID; ++j) s += fc3W[o * HID + j] * g_b12[j];
        g_bc[o] = s + fc3b[o];
    }
}

// ---------------- f32x2 SIMT GEMM ----------------
template<int TN, int MT, int AMODE, int OMODE>
__global__ void __launch_bounds__(256)
gemm_kernel(const float* __restrict__ Ap, const float* __restrict__ Bw,
            const float* __restrict__ bias1, const float* __restrict__ bias2,
            float* __restrict__ Cp, int K) {
    __shared__ __align__(16) float As[16][128];
    __shared__ __align__(16) float Bs[16][TN];
    constexpr int NX = TN / 8;
    const int tid = threadIdx.x;
    const int bm = blockIdx.x * 128;
    const int bn = blockIdx.y * TN;
    const int tx = tid % NX, ty = tid / NX;

    const float* arow[2]; int amm[2], akq[2];
#pragma unroll
    for (int it = 0; it < 2; ++it) {
        int slot = tid + it * 256;
        amm[it] = slot >> 2; akq[it] = slot & 3;
        int m = bm + amm[it];
        if (AMODE) arow[it] = Ap + ((size_t)(m & 63) * SEQ + (m >> 6)) * K;
        else       arow[it] = Ap + (size_t)m * K;
    }
    constexpr int BLD = TN / 64;
    const float* brow[BLD]; int bnn[BLD], bkq[BLD];
#pragma unroll
    for (int it = 0; it < BLD; ++it) {
        int slot = tid + it * 256;
        bnn[it] = slot >> 2; bkq[it] = slot & 3;
        brow[it] = Bw + (size_t)(bn + bnn[it]) * K;
    }

    ull acc[MT][4];
#pragma unroll
    for (int i = 0; i < MT; ++i)
#pragma unroll
        for (int j = 0; j < 4; ++j) acc[i][j] = 0ull;

    uint32_t bs_base = (uint32_t)__cvta_generic_to_shared(&Bs[0][0]);

    for (int k0 = 0; k0 < K; k0 += 16) {
#pragma unroll
        for (int it = 0; it < 2; ++it) {
            float4 v = *(const float4*)(arow[it] + k0 + akq[it] * 4);
            As[akq[it] * 4 + 0][amm[it]] = v.x;
            As[akq[it] * 4 + 1][amm[it]] = v.y;
            As[akq[it] * 4 + 2][amm[it]] = v.z;
            As[akq[it] * 4 + 3][amm[it]] = v.w;
        }
#pragma unroll
        for (int it = 0; it < BLD; ++it) {
            float4 v = *(const float4*)(brow[it] + k0 + bkq[it] * 4);
            Bs[bkq[it] * 4 + 0][bnn[it]] = v.x;
            Bs[bkq[it] * 4 + 1][bnn[it]] = v.y;
            Bs[bkq[it] * 4 + 2][bnn[it]] = v.z;
            Bs[bkq[it] * 4 + 3][bnn[it]] = v.w;
        }
        __syncthreads();
#pragma unroll
        for (int kk = 0; kk < 16; ++kk) {
            ull b0, b1, b2, b3;
            uint32_t ba = bs_base + (uint32_t)((kk * TN + tx * 8) * 4);
            lds_v2u64(b0, b1, ba);
            lds_v2u64(b2, b3, ba + 16);
            float av[MT];
#pragma unroll
            for (int q = 0; q < MT; q += 4) {
                float4 a4 = *(const float4*)&As[kk][ty * MT + q];
                av[q] = a4.x; av[q + 1] = a4.y; av[q + 2] = a4.z; av[q + 3] = a4.w;
            }
#pragma unroll
            for (int i = 0; i < MT; ++i) {
                ull ad = pack2(av[i], av[i]);
                ffma2(acc[i][0], ad, b0);
                ffma2(acc[i][1], ad, b1);
                ffma2(acc[i][2], ad, b2);
                ffma2(acc[i][3], ad, b3);
            }
        }
        __syncthreads();
    }

    float bb[8];
#pragma unroll
    for (int j = 0; j < 8; ++j) {
        int n = bn + tx * 8 + j;
        float v = bias1 ? bias1[n] : 0.f;
        if (bias2) v += bias2[n];
        bb[j] = v;
    }
#pragma unroll
    for (int i = 0; i < MT; ++i) {
        int m = bm + ty * MT + i;
        float2 p0 = unpack2(acc[i][0]), p1 = unpack2(acc[i][1]);
        float2 p2 = unpack2(acc[i][2]), p3 = unpack2(acc[i][3]);
        float4 v0 = {p0.x + bb[0], p0.y + bb[1], p1.x + bb[2], p1.y + bb[3]};
        float4 v1 = {p2.x + bb[4], p2.y + bb[5], p3.x + bb[6], p3.y + bb[7]};
        float* dst;
        if (OMODE) dst = Cp + ((size_t)(m & 63) * SEQ + (m >> 6)) * OUTD + bn + tx * 8;
        else       dst = Cp + (size_t)m * ((size_t)gridDim.y * TN) + bn + tx * 8;
        *(float4*)dst = v0;
        *(float4*)(dst + 4) = v1;
    }
}

// ---------------- persistent RNN scan, k-split partial exchange ----------------
// 2-CTA cluster per batch. CTA rank owns h rows [rank*128, rank*128+128) and the
// MATCHING k-half of W for ALL 256 output rows: thread tid (0..255) holds
// W[tid][rank*128 .. rank*128+128) in registers (64 f32x2). Per step:
//   dot over LOCAL h-half only (no wait), push partials for peer rows via DSMEM,
//   own rows wait for peer partials, tanh, store h locally. h never crosses.
__device__ __forceinline__ void cluster_sync_() {
    asm volatile("barrier.cluster.arrive.aligned;" ::: "memory");
    asm volatile("barrier.cluster.wait.aligned;" ::: "memory");
}
__device__ __forceinline__ void mbar_wait_cluster(uint32_t mb, int ph) {
    asm volatile(
        "{\n\t.reg .pred P;\n"
        "W1_%=:\n\t"
        "mbarrier.try_wait.parity.acquire.cluster.shared::cta.b64 P, [%0], %1, 0x989680;\n\t"
        "@P bra W2_%=;\n\t"
        "bra W1_%=;\n"
        "W2_%=:\n\t}"
        :: "r"(mb), "r"(ph) : "memory");
}

__global__ void __cluster_dims__(2, 1, 1) __launch_bounds__(256, 1)
scan_kernel(const float* __restrict__ A, const float* __restrict__ W, float* __restrict__ Hout) {
    __shared__ __align__(16) float h_sm[2][128];     // local h half, double buffered
    __shared__ __align__(16) float recv_sm[2][128];  // incoming partials for own rows
    __shared__ __align__(8) ull mbar[2];
    const int tid = threadIdx.x;
    uint32_t rank;
    asm("mov.u32 %0, %%cluster_ctarank;" : "=r"(rank));
    const int b = blockIdx.x >> 1;
    const int jl = tid & 127;
    const bool own = ((uint32_t)(tid >> 7) == rank);   // warp-uniform

    // register-resident W slice: row tid, k in [rank*128, rank*128+128)
    ull wreg[64];
    {
        const float* ws = W + (size_t)tid * HID + rank * 128;
#pragma unroll
        for (int i = 0; i < 64; i += 2) {
            float4 v = *(const float4*)(ws + i * 2);
            wreg[i] = pack2(v.x, v.y); wreg[i + 1] = pack2(v.z, v.w);
        }
    }

    uint32_t h_local = (uint32_t)__cvta_generic_to_shared(&h_sm[0][0]);
    uint32_t recv_local = (uint32_t)__cvta_generic_to_shared(&recv_sm[0][0]);
    uint32_t mb_local = (uint32_t)__cvta_generic_to_shared(&mbar[0]);
    uint32_t recv_peer, mb_peer;
    asm("mapa.shared::cluster.u32 %0, %1, %2;" : "=r"(recv_peer) : "r"(recv_local), "r"(rank ^ 1u));
    asm("mapa.shared::cluster.u32 %0, %1, %2;" : "=r"(mb_peer) : "r"(mb_local), "r"(rank ^ 1u));

    if (tid == 0) {
        asm volatile("mbarrier.init.shared.b64 [%0], %1;" :: "r"(mb_local), "r"(4) : "memory");
        asm volatile("mbarrier.init.shared.b64 [%0], %1;" :: "r"(mb_local + 8), "r"(4) : "memory");
    }
    __syncthreads();
    cluster_sync_();  // peer mbarriers live before any remote arrive

    const float* Abase = A + (size_t)b * HID + tid;   // only used by own rows
    float* Hbase = Hout + (size_t)b * HID + tid;

    float acur = 0.f, anext = 0.f;
    // ---- t = 0: h = tanh(A[0]) ----
    if (own) {
        acur = __ldg(Abase);
        float hv = tanh_fast(acur);
        h_sm[1][jl] = hv;
        Hbase[0] = hv;
        anext = __ldg(Abase + (size_t)BATCH * HID);
    }
    __syncthreads();

    int ph0 = 0, ph1 = 0;
    for (int t = 1; t < SEQ; ++t) {
        const int p = t & 1;
        acur = anext;
        if (own) {
            int tn = (t + 1 < SEQ) ? (t + 1) : (SEQ - 1);
            anext = __ldg(Abase + (size_t)tn * (BATCH * HID));
        }
        // ---- dot over local 128-wide h-half (h[t-1] in h_sm[p]) ----
        uint32_t hb = h_local + (uint32_t)(p * 128 * 4);
        ull a0 = 0ull, a1 = 0ull, a2 = 0ull, a3 = 0ull;
#pragma unroll
        for (int i = 0; i < 32; ++i) {           // 32 iters x 4 floats = 128 h values
            ull x0, x1;
            lds_v2u64(x0, x1, hb + (uint32_t)(i * 16));
            if (i & 1) { ffma2(a2, wreg[2 * i], x0); ffma2(a3, wreg[2 * i + 1], x1); }
            else       { ffma2(a0, wreg[2 * i], x0); ffma2(a1, wreg[2 * i + 1], x1); }
        }
        float2 s0 = unpack2(a0), s1 = unpack2(a1), s2 = unpack2(a2), s3 = unpack2(a3);
        float part = ((s0.x + s0.y) + (s1.x + s1.y)) + ((s2.x + s2.y) + (s3.x + s3.y));

        if (!own) {
            // push partial for peer's own-row jl into peer recv buffer p
            uint32_t ra = recv_peer + (uint32_t)((p * 128 + jl) * 4);
            asm volatile("st.shared::cluster.f32 [%0], %1;" :: "r"(ra), "f"(part) : "memory");
            __syncwarp();
            if ((tid & 31) == 0) {
                uint32_t rm = mb_peer + (uint32_t)(p * 8);
                asm volatile("mbarrier.arrive.release.cluster.shared::cluster.b64 _, [%0];"
                             :: "r"(rm) : "memory");
            }
        } else {
            // wait for peer's 4 pushing warps, then finalize h
            if (p) { mbar_wait_cluster(mb_local + 8, ph1); ph1 ^= 1; }
            else   { mbar_wait_cluster(mb_local,     ph0); ph0 ^= 1; }
            float s = part + recv_sm[p][jl] + acur;
            float hv = tanh_fast(s);
            h_sm[p ^ 1][jl] = hv;
            Hbase[(size_t)t * (BATCH * HID)] = hv;
        }
        __syncthreads();  // new h visible; closes reuse window on h_sm[p]
    }
    cluster_sync_();  // keep smem alive for in-flight peer traffic
}

// ---------------- launcher ----------------
extern "C" void kernel_launch(void* const* d_in, const int* in_sizes, int n_in,
                              void* d_out, int out_size) {
    const float* x    = (const float*)d_in[0];
    const float* U0   = (const float*)d_in[1];
    const float* bU0  = (const float*)d_in[2];
    const float* W0   = (const float*)d_in[3];
    const float* bW0  = (const float*)d_in[4];
    const float* U1   = (const float*)d_in[5];
    const float* bU1  = (const float*)d_in[6];
    const float* W1   = (const float*)d_in[7];
    const float* bW1  = (const float*)d_in[8];
    const float* fc1W = (const float*)d_in[9];
    const float* fc1b = (const float*)d_in[10];
    const float* fc2W = (const float*)d_in[11];
    const float* fc2b = (const float*)d_in[12];
    const float* fc3W = (const float*)d_in[13];
    const float* fc3b = (const float*)d_in[14];
    float* out = (float*)d_out;

    float *pA, *pH, *pWc, *pbc;
    cudaGetSymbolAddress((void**)&pA, g_bufA);
    cudaGetSymbolAddress((void**)&pH, g_bufH);
    cudaGetSymbolAddress((void**)&pWc, g_Wc);
    cudaGetSymbolAddress((void**)&pbc, g_bc);

    combine1_kernel<<<HID, HID>>>(fc2W, fc1W, fc1b, fc2b);
    combine2_kernel<<<OUTD, HID>>>(fc3W, fc3b);

    // A0[t,b,:] = x[b,t,:] @ U0^T + bU0 + bW0
    gemm_kernel<128, 8, 1, 0><<<dim3(M_ROWS / 128, HID / 128), 256>>>(x, U0, bU0, bW0, pA, IND);
    scan_kernel<<<BATCH * 2, 256>>>(pA, W0, pH);
    // A1 = h0_all @ U1^T + bU1 + bW1
    gemm_kernel<128, 8, 0, 0><<<dim3(M_ROWS / 128, HID / 128), 256>>>(pH, U1, bU1, bW1, pA, HID);
    scan_kernel<<<BATCH * 2, 256>>>(pA, W1, pH);
    // head: out[b,t,:] = outs[t,b,:] @ Wc^T + bc (N=64)
    gemm_kernel<64, 4, 0, 1><<<dim3(M_ROWS / 128, 1), 256>>>(pH, pWc, pbc, nullptr, out, HID);
}